// round 9
// baseline (speedup 1.0000x reference)
#include <cuda_runtime.h>

// selfAttn2d round 9: phase-3 refactored as pure GEMM (relc_tf32 @ wd) + tiny
// fp32 e-contraction; q/k stored transposed for LDS.128 reads in P3-B and P4.

__device__ __forceinline__ unsigned int f2tf32(float x) {
    unsigned int r; asm("cvt.rna.tf32.f32 %0, %1;" : "=r"(r) : "f"(x)); return r;
}
__device__ __forceinline__ unsigned int fu(float x) { return __float_as_uint(x); }
__device__ __forceinline__ void mma_tf32(float& d0, float& d1, float& d2, float& d3,
                                         unsigned int a0, unsigned int a1,
                                         unsigned int a2, unsigned int a3,
                                         unsigned int b0, unsigned int b1) {
    asm("mma.sync.aligned.m16n8k8.row.col.f32.tf32.tf32.f32 "
        "{%0,%1,%2,%3},{%4,%5,%6,%7},{%8,%9},{%0,%1,%2,%3};"
        : "+f"(d0), "+f"(d1), "+f"(d2), "+f"(d3)
        : "r"(a0), "r"(a1), "r"(a2), "r"(a3), "r"(b0), "r"(b1));
}

// Prepped tables.
__device__ float g_wa1[12 * 8 * 32 * 4];   // qkv A-frags  [mt][oct][lane][r], tf32
__device__ float g_wa2[4 * 72 * 32 * 4];   // conv A-frags [mt][oct][lane][r], tf32
__device__ float g_wd3[64 * 1024];         // w_deconv B-frags [n][w][koct][npair][lane][4], tf32
__device__ float g_wpt[64 * 64];           // w_proj [j][o]

__global__ void prep_kernel(const float* __restrict__ wq,
                            const float* __restrict__ wk,
                            const float* __restrict__ wv,
                            const float* __restrict__ w_rel,
                            const float* __restrict__ w_deconv,
                            const float* __restrict__ w_proj)
{
    const int i0 = blockIdx.x * blockDim.x + threadIdx.x;
    const int stride = gridDim.x * blockDim.x;
    for (int i = i0; i < 4096; i += stride) {
        int o = i >> 6, c = i & 63;
        g_wpt[(c << 6) | o] = w_proj[i];
    }
    for (int j = i0; j < 12288; j += stride) {
        int r = j & 3, lane = (j >> 2) & 31, oct = (j >> 7) & 7, mt = j >> 10;
        int row = (lane >> 2) + ((r & 1) << 3);
        int k   = oct * 8 + (lane & 3) + ((r >> 1) << 2);
        const float* W = (mt < 4) ? wq : (mt < 8) ? wk : wv;
        g_wa1[j] = __uint_as_float(f2tf32(W[((mt & 3) * 16 + row) * 64 + k]));
    }
    for (int j = i0; j < 36864; j += stride) {
        int r = j & 3, lane = (j >> 2) & 31;
        int mo = j >> 7;
        int mt = mo / 72, oct = mo - mt * 72;
        int u = oct >> 3, jj = oct & 7;
        int ch = mt * 16 + (lane >> 2) + ((r & 1) << 3);
        int c  = jj * 8 + (lane & 3) + ((r >> 1) << 2);
        g_wa2[j] = __uint_as_float(f2tf32(w_rel[ch * 576 + c * 9 + u]));
    }
    // g_wd3: B[k=ch][c2] for GEMM M = relc @ wd_n; c2 = bd*16 + e globally.
    // idx = ((((n*8 + w)*8 + koct)*2 + npair)*32 + lane)*4 + v
    for (int j = i0; j < 65536; j += stride) {
        int v    = j & 3;
        int lane = (j >> 2) & 31;
        int rest = j >> 7;            // ((n*8+w)*8+koct)*2+npair
        int npair = rest & 1;
        int koct  = (rest >> 1) & 7;
        int w2    = (rest >> 4) & 7;
        int n     = rest >> 7;
        int noct = npair * 2 + (v >> 1);
        int ch   = koct * 8 + (lane & 3) + (v & 1) * 4;
        int c2   = w2 * 32 + noct * 8 + (lane >> 2);
        int e    = c2 & 15;
        int bd   = c2 >> 4;
        g_wd3[j] = __uint_as_float(f2tf32(w_deconv[ch * 1024 + (n * 16 + e) * 16 + bd]));
    }
}

// Dynamic smem layout (floats), total 20992 (83968 B):
//   PB(pi)=pi*4608 : per-patch scratch (4608)
//     P0-P2 : sp_pad [sig(c)][37] = PB+0..2367 ; sp_lin [c][24] = PB+2368..3903
//     P2    : partials [8w][16][18] = PB+0..2303 (after inner sync)
//     P3-A  : M_n [16 ac][260] = PB+0..4159
//     P4    : hbuf PB+0..1023, wbuf PB+1024..2047, abuf PB+2048..3071
//   QT=9216  : q_t[pi][n][ac][20] (pi*1280 + n*320)
//   KT=11776 : k_t same
//   VS=14336 : v_s[pi][n][dv][18] (pi*1152 + n*288)
//   RC=16640 : relc_t[pi][ac][68] (pi*1088), values pre-cvt'd to tf32
//   CS=18816 : csum[pi][64]
//   RL=18944 : rl[pi][n][ac][16] (pi*1024)
#define SMEM_FLOATS 20992
#define QT 9216
#define KT 11776
#define VS 14336
#define RC 16640
#define CS 18816
#define RL 18944

__global__ __launch_bounds__(256, 2)
void selfattn2d_kernel(const float* __restrict__ x,
                       const float* __restrict__ w_sf1,
                       const float* __restrict__ b_sf1,
                       const float* __restrict__ w_sf2,
                       const float* __restrict__ b_sf2,
                       const float* __restrict__ b_proj,
                       float* __restrict__ out)
{
    extern __shared__ __align__(16) float S[];
    const int bid = blockIdx.x;
    const int b   = bid >> 9;
    const int t  = threadIdx.x;
    const int lane = t & 31;
    const int w    = t >> 5;

    int oys[2], oxs[2];
#pragma unroll
    for (int pi = 0; pi < 2; pi++) {
        int pb = bid * 2 + pi;
        oys[pi] = (pb >> 5) & 31;
        oxs[pi] = pb & 31;
    }

    // ---------------- Phase 0: load both patches ----------------
    {
        const float* xb = x + b * (64 * 64 * 64);
        for (int idx = t; idx < 4608; idx += 256) {
            int pi = (idx >= 2304) ? 1 : 0;
            int local = idx - pi * 2304;
            int c  = local / 36;
            int r  = local - c * 36;
            int ii = r / 6;
            int jj = r - ii * 6;
            int gy = oys[pi] * 2 + ii - 2;
            int gx = oxs[pi] * 2 + jj - 2;
            float val = 0.f;
            bool inpatch = (ii >= 1 && ii <= 4 && jj >= 1 && jj <= 4);
            if (inpatch && gy >= 0 && gy < 64 && gx >= 0 && gx < 64)
                val = xb[c * 4096 + gy * 64 + gx];
            val = __uint_as_float(f2tf32(val));
            S[pi * 4608 + ((c & 15) * 4 + (c >> 4)) * 37 + r] = val;
            if (inpatch)
                S[pi * 4608 + 2368 + c * 24 + (ii - 1) * 4 + (jj - 1)] = val;
        }
    }
    __syncthreads();

    // ---------------- Phase 1: q/k/v on tensor cores ----------------
    // tiles 0-3: q (transposed store to q_t), 4-7: k (to k_t), 8-11: v (to v_s)
    {
        const int base0 = (lane & 3) * 24 + (lane >> 2);
        const int g = lane >> 2, tg = lane & 3;
        const int nt = (w < 4) ? 1 : 2;
#pragma unroll
        for (int ti = 0; ti < 2; ti++) {
            if (ti >= nt) break;
            const int mt = (ti == 0) ? w : (w + 4);
            float acc[2][8];
#pragma unroll
            for (int pi = 0; pi < 2; pi++)
#pragma unroll
                for (int p = 0; p < 8; p++) acc[pi][p] = 0.f;
            const float4* wa = ((const float4*)g_wa1) + mt * 256 + lane;
#pragma unroll
            for (int oct = 0; oct < 8; oct++) {
                float4 A4 = wa[oct * 32];
#pragma unroll
                for (int pi = 0; pi < 2; pi++) {
                    const float* bp = S + pi * 4608 + 2368 + base0 + oct * 192;
                    float b0 = bp[0], b1 = bp[96];
                    float c0 = bp[8], c1 = bp[104];
                    mma_tf32(acc[pi][0], acc[pi][1], acc[pi][2], acc[pi][3],
                             fu(A4.x), fu(A4.y), fu(A4.z), fu(A4.w), fu(b0), fu(b1));
                    mma_tf32(acc[pi][4], acc[pi][5], acc[pi][6], acc[pi][7],
                             fu(A4.x), fu(A4.y), fu(A4.z), fu(A4.w), fu(c0), fu(c1));
                }
            }
            if (mt < 8) {
                // C[row=e][col=ac] -> transposed store [ac][e], stride 20
                const float sc = (mt < 4) ? 0.25f : 1.0f;
                const int n2 = mt & 3;
                float* tb = S + ((mt < 4) ? QT : KT) + n2 * 320;
#pragma unroll
                for (int pi = 0; pi < 2; pi++) {
                    float* bp2 = tb + pi * 1280;
                    bp2[(2 * tg) * 20 + g]         = acc[pi][0] * sc;
                    bp2[(2 * tg + 1) * 20 + g]     = acc[pi][1] * sc;
                    bp2[(2 * tg) * 20 + g + 8]     = acc[pi][2] * sc;
                    bp2[(2 * tg + 1) * 20 + g + 8] = acc[pi][3] * sc;
                    bp2[(2 * tg + 8) * 20 + g]         = acc[pi][4] * sc;
                    bp2[(2 * tg + 9) * 20 + g]         = acc[pi][5] * sc;
                    bp2[(2 * tg + 8) * 20 + g + 8]     = acc[pi][6] * sc;
                    bp2[(2 * tg + 9) * 20 + g + 8]     = acc[pi][7] * sc;
                }
            } else {
                const int n2 = mt - 8;
                const int col = 2 * tg;
#pragma unroll
                for (int pi = 0; pi < 2; pi++) {
                    float* dst = S + VS + pi * 1152 + n2 * 288;
                    *(float2*)(dst + g * 18 + col)           = make_float2(acc[pi][0], acc[pi][1]);
                    *(float2*)(dst + (g + 8) * 18 + col)     = make_float2(acc[pi][2], acc[pi][3]);
                    *(float2*)(dst + g * 18 + col + 8)       = make_float2(acc[pi][4], acc[pi][5]);
                    *(float2*)(dst + (g + 8) * 18 + col + 8) = make_float2(acc[pi][6], acc[pi][7]);
                }
            }
        }
    }

    // ---------------- Phase 2: rel_c conv on tensor cores ----------------
    {
        const int mt = w & 3, halfk = w >> 2;
        float acc[2][8];
#pragma unroll
        for (int pi = 0; pi < 2; pi++)
#pragma unroll
            for (int p = 0; p < 8; p++) acc[pi][p] = 0.f;
        const float4* wa = ((const float4*)g_wa2) + mt * 2304 + lane;
        const int q37 = (lane & 3) * 148;
        const int ac = lane >> 2;
        const int Pa = (ac >> 2) * 6 + (ac & 3);
#pragma unroll
        for (int u = 0; u < 9; u++) {
            bool mine = (halfk == 0) ? (u < 5) : (u >= 5);
            if (mine) {
                const int P = Pa + (u / 3) * 6 + (u % 3);
#pragma unroll
                for (int j = 0; j < 8; j++) {
                    float4 A4 = wa[(u * 8 + j) * 32];
                    const int boff = q37 + (j & 1) * 1184 + (j >> 1) * 37 + P;
#pragma unroll
                    for (int pi = 0; pi < 2; pi++) {
                        const float* sp = S + pi * 4608 + boff;
                        float b0 = sp[0],  b1 = sp[592];
                        float c0 = sp[12], c1 = sp[604];
                        mma_tf32(acc[pi][0], acc[pi][1], acc[pi][2], acc[pi][3],
                                 fu(A4.x), fu(A4.y), fu(A4.z), fu(A4.w), fu(b0), fu(b1));
                        mma_tf32(acc[pi][4], acc[pi][5], acc[pi][6], acc[pi][7],
                                 fu(A4.x), fu(A4.y), fu(A4.z), fu(A4.w), fu(c0), fu(c1));
                    }
                }
            }
        }
        __syncthreads();     // all patch reads complete before partial overwrite
        const int row = lane >> 2, col = 2 * (lane & 3);
#pragma unroll
        for (int pi = 0; pi < 2; pi++) {
            float* rp = S + pi * 4608 + w * 288;
            *(float2*)(rp + row * 18 + col)           = make_float2(acc[pi][0], acc[pi][1]);
            *(float2*)(rp + (row + 8) * 18 + col)     = make_float2(acc[pi][2], acc[pi][3]);
            *(float2*)(rp + row * 18 + col + 8)       = make_float2(acc[pi][4], acc[pi][5]);
            *(float2*)(rp + (row + 8) * 18 + col + 8) = make_float2(acc[pi][6], acc[pi][7]);
        }
    }
    __syncthreads();
    // reduce u-halves into relc_t[pi][ac][ch], pre-converted to tf32
    {
#pragma unroll
        for (int it = 0; it < 2; it++) {
            int task = t + it * 256;            // 512: pi(2) x ac(16) x chq(16)
            int pi = task >> 8;
            int rem = task & 255;
            int ac2 = rem >> 4;
            int chq = rem & 15;
            int mt2 = chq >> 2;
            const float* pa = S + pi * 4608 + mt2 * 288 + ((chq & 3) * 4) * 18 + ac2;
            const float* pb2 = pa + 4 * 288;
            float4 v4;
            v4.x = __uint_as_float(f2tf32(pa[0]  + pb2[0]));
            v4.y = __uint_as_float(f2tf32(pa[18] + pb2[18]));
            v4.z = __uint_as_float(f2tf32(pa[36] + pb2[36]));
            v4.w = __uint_as_float(f2tf32(pa[54] + pb2[54]));
            *(float4*)(S + RC + pi * 1088 + ac2 * 68 + chq * 4) = v4;
        }
    }
    __syncthreads();

    // ---------------- Phase 3: per-n GEMM M = relc @ wd_n, then e-contraction ----------------
    {
        const int g = lane >> 2, tg = lane & 3;
        const int pi2 = t >> 7, tl = t & 127;
        const int acB = tl >> 3, bdp = tl & 7;
        for (int n = 0; n < 4; n++) {
            // --- stage A: warp w computes M cols [w*32, w*32+32) ---
            float acc[2][4][4];
#pragma unroll
            for (int pi = 0; pi < 2; pi++)
#pragma unroll
                for (int no = 0; no < 4; no++)
#pragma unroll
                    for (int r = 0; r < 4; r++) acc[pi][no][r] = 0.f;
            const float4* wd4 = ((const float4*)g_wd3) + ((n * 8 + w) * 8) * 2 * 32 + lane;
#pragma unroll
            for (int koct = 0; koct < 8; koct++) {
                unsigned int a[2][4];
#pragma unroll
                for (int pi = 0; pi < 2; pi++) {
                    const float* rc = S + RC + pi * 1088 + koct * 8 + tg;
                    a[pi][0] = fu(rc[g * 68]);
                    a[pi][1] = fu(rc[(g + 8) * 68]);
                    a[pi][2] = fu(rc[g * 68 + 4]);
                    a[pi][3] = fu(rc[(g + 8) * 68 + 4]);
                }
#pragma unroll
                for (int npair = 0; npair < 2; npair++) {
                    float4 B4 = wd4[(koct * 2 + npair) * 32];
#pragma unroll
                    for (int pi = 0; pi < 2; pi++) {
                        mma_tf32(acc[pi][npair * 2][0], acc[pi][npair * 2][1],
                                 acc[pi][npair * 2][2], acc[pi][npair * 2][3],
                                 a[pi][0], a[pi][1], a[pi][2], a[pi][3],
                                 fu(B4.x), fu(B4.y));
                        mma_tf32(acc[pi][npair * 2 + 1][0], acc[pi][npair * 2 + 1][1],
                                 acc[pi][npair * 2 + 1][2], acc[pi][npair * 2 + 1][3],
                                 a[pi][0], a[pi][1], a[pi][2], a[pi][3],
                                 fu(B4.z), fu(B4.w));
                    }
                }
            }
#pragma unroll
            for (int pi = 0; pi < 2; pi++) {
                float* M = S + pi * 4608;
#pragma unroll
                for (int no = 0; no < 4; no++) {
                    const int col = w * 32 + no * 8 + 2 * tg;
                    *(float2*)(M + g * 260 + col)       = make_float2(acc[pi][no][0], acc[pi][no][1]);
                    *(float2*)(M + (g + 8) * 260 + col) = make_float2(acc[pi][no][2], acc[pi][no][3]);
                }
            }
            __syncthreads();
            // --- stage B: rl[n][ac][bd] = sum_e q_t[n][ac][e] * M[ac][bd*16+e] ---
            {
                const float* M = S + pi2 * 4608 + acB * 260;
                const float4* q4 = (const float4*)(S + QT + pi2 * 1280 + n * 320 + acB * 20);
                float4 q0 = q4[0], q1 = q4[1], q2 = q4[2], q3 = q4[3];
                float* rl = S + RL + pi2 * 1024 + n * 256 + acB * 16;
#pragma unroll
                for (int u2 = 0; u2 < 2; u2++) {
                    const int bd = bdp * 2 + u2;
                    const float4* m4 = (const float4*)(M + bd * 16);
                    float4 m0 = m4[0], m1 = m4[1], m2 = m4[2], m3 = m4[3];
                    float s = q0.x * m0.x + q0.y * m0.y + q0.z * m0.z + q0.w * m0.w
                            + q1.x * m1.x + q1.y * m1.y + q1.z * m1.z + q1.w * m1.w
                            + q2.x * m2.x + q2.y * m2.y + q2.z * m2.z + q2.w * m2.w
                            + q3.x * m3.x + q3.y * m3.y + q3.z * m3.z + q3.w * m3.w;
                    rl[bd] = s;
                }
            }
            __syncthreads();
        }
    }

    // ---------------- Phase 4: MLP + softmax + attention (256 threads) ----------------
    {
        const int pi = t >> 7, tl = t & 127;
        const int n = tl >> 5, p = (tl >> 1) & 15, hf = tl & 1;
        const float4* q4 = (const float4*)(S + QT + pi * 1280 + n * 320 + p * 20);
        const float4* k4 = (const float4*)(S + KT + pi * 1280 + n * 320 + p * 20);
        float qv[16], kv[16];
#pragma unroll
        for (int i4 = 0; i4 < 4; i4++) {
            float4 a = q4[i4], c = k4[i4];
            qv[4 * i4] = a.x; qv[4 * i4 + 1] = a.y; qv[4 * i4 + 2] = a.z; qv[4 * i4 + 3] = a.w;
            kv[4 * i4] = c.x; kv[4 * i4 + 1] = c.y; kv[4 * i4 + 2] = c.z; kv[4 * i4 + 3] = c.w;
        }
        float h1v[8];
#pragma unroll
        for (int hh = 0; hh < 8; hh++) {
            int h = hf * 8 + hh;
            float s = b_sf1[h];
            const float* w1r = w_sf1 + h * 32;
#pragma unroll
            for (int d = 0; d < 16; d++) s += w1r[d] * qv[d];
#pragma unroll
            for (int d = 0; d < 16; d++) s += w1r[16 + d] * kv[d];
            h1v[hh] = tanhf(s);
        }
        float* hb = S + pi * 4608 + (n * 16 + p) * 16 + hf * 8;
        *(float4*)hb       = make_float4(h1v[0], h1v[1], h1v[2], h1v[3]);
        *(float4*)(hb + 4) = make_float4(h1v[4], h1v[5], h1v[6], h1v[7]);
    }
    __syncthreads();
    {
        const int pi = t >> 7, tl = t & 127;
        const int n = tl >> 5, p = (tl >> 1) & 15, hf = tl & 1;
        float hv[16];
        const float4* hb4 = (const float4*)(S + pi * 4608 + (n * 16 + p) * 16);
#pragma unroll
        for (int i4 = 0; i4 < 4; i4++) {
            float4 v4 = hb4[i4];
            hv[4 * i4] = v4.x; hv[4 * i4 + 1] = v4.y; hv[4 * i4 + 2] = v4.z; hv[4 * i4 + 3] = v4.w;
        }
        const float* rp = S + RL + pi * 1024 + n * 256 + p * 16;
        float lg[8];
        float mx = -1e30f;
#pragma unroll
        for (int mm = 0; mm < 8; mm++) {
            int m = hf * 8 + mm;
            float s = b_sf2[m];
            const float* w2r = w_sf2 + m * 16;
#pragma unroll
            for (int h = 0; h < 16; h++) s += w2r[h] * hv[h];
            s += rp[m];
            lg[mm] = s;
            mx = fmaxf(mx, s);
        }
        mx = fmaxf(mx, __shfl_xor_sync(0xffffffffu, mx, 1));
        float den = 0.f;
#pragma unroll
        for (int mm = 0; mm < 8; mm++) { lg[mm] = __expf(lg[mm] - mx); den += lg[mm]; }
        den += __shfl_xor_sync(0xffffffffu, den, 1);
        const float inv = 1.0f / den;
        float* wb = S + pi * 4608 + 1024 + (n * 16 + p) * 16 + hf * 8;
        *(float4*)wb       = make_float4(lg[0] * inv, lg[1] * inv, lg[2] * inv, lg[3] * inv);
        *(float4*)(wb + 4) = make_float4(lg[4] * inv, lg[5] * inv, lg[6] * inv, lg[7] * inv);
    }
    __syncthreads();
    {
        const int pi = t >> 7, tl = t & 127;
        const int n = tl >> 5, p = (tl >> 1) & 15, hf = tl & 1;
        float wv_[16];
        const float4* wb4 = (const float4*)(S + pi * 4608 + 1024 + (n * 16 + p) * 16);
#pragma unroll
        for (int i4 = 0; i4 < 4; i4++) {
            float4 v4 = wb4[i4];
            wv_[4 * i4] = v4.x; wv_[4 * i4 + 1] = v4.y; wv_[4 * i4 + 2] = v4.z; wv_[4 * i4 + 3] = v4.w;
        }
        float av[8];
        const float* vbase = S + VS + pi * 1152 + n * 288;
#pragma unroll
        for (int dd = 0; dd < 8; dd++) {
            int dv = hf * 8 + dd;
            const float2* vr = (const float2*)(vbase + dv * 18);
            float a = 0.f;
#pragma unroll
            for (int m2 = 0; m2 < 8; m2++) {
                float2 vv = vr[m2];
                a += wv_[2 * m2] * vv.x + wv_[2 * m2 + 1] * vv.y;
            }
            av[dd] = a;
        }
        float* ab = S + pi * 4608 + 2048 + (n * 16 + p) * 16 + hf * 8;
        *(float4*)ab       = make_float4(av[0], av[1], av[2], av[3]);
        *(float4*)(ab + 4) = make_float4(av[4], av[5], av[6], av[7]);
    }
    __syncthreads();
    if (t < 128) {
        const int pi = t >> 6, tl = t & 63;
        const int plo = tl >> 4;
        const int dv  = tl & 15;
        const float* ab = S + pi * 4608 + 2048;
        float s = 0.f;
#pragma unroll
        for (int n2 = 0; n2 < 4; n2++)
#pragma unroll
            for (int ph = 0; ph < 4; ph++)
                s += ab[(n2 * 16 + ph * 4 + plo) * 16 + dv];
        S[CS + pi * 64 + tl] = s;
    }
    __syncthreads();

    // ---------------- Phase 5: projection + sum ----------------
    if (t < 128) {
        const int pi = t >> 6, o = t & 63;
        const float* cs = S + CS + pi * 64;
        float acc = 16.0f * b_proj[o];
#pragma unroll 8
        for (int j = 0; j < 64; j++) acc += cs[j] * g_wpt[(j << 6) | o];
        out[b * 65536 + o * 1024 + oys[pi] * 32 + oxs[pi]] = acc;
    }
}

extern "C" void kernel_launch(void* const* d_in, const int* in_sizes, int n_in,
                              void* d_out, int out_size)
{
    (void)in_sizes; (void)n_in; (void)out_size;
    cudaFuncSetAttribute(selfattn2d_kernel,
                         cudaFuncAttributeMaxDynamicSharedMemorySize,
                         SMEM_FLOATS * sizeof(float));
    prep_kernel<<<64, 256>>>(
        (const float*)d_in[1],  // wq
        (const float*)d_in[2],  // wk
        (const float*)d_in[3],  // wv
        (const float*)d_in[4],  // w_rel
        (const float*)d_in[5],  // w_deconv
        (const float*)d_in[10]);// w_proj
    selfattn2d_kernel<<<2048, 256, SMEM_FLOATS * sizeof(float)>>>(
        (const float*)d_in[0],  // x
        (const float*)d_in[6],  // w_sf1
        (const float*)d_in[7],  // b_sf1
        (const float*)d_in[8],  // w_sf2
        (const float*)d_in[9],  // b_sf2
        (const float*)d_in[11], // b_proj
        (float*)d_out);
}

// round 10
// speedup vs baseline: 1.3107x; 1.3107x over previous
#include <cuda_runtime.h>

// selfAttn2d round 10: phase 3 = GEMM (relc_tf32 @ wd) with the e-contraction
// done IN REGISTERS on the mma fragments (quad shfl reduce) — no M staging.

__device__ __forceinline__ unsigned int f2tf32(float x) {
    unsigned int r; asm("cvt.rna.tf32.f32 %0, %1;" : "=r"(r) : "f"(x)); return r;
}
__device__ __forceinline__ unsigned int fu(float x) { return __float_as_uint(x); }
__device__ __forceinline__ void mma_tf32(float& d0, float& d1, float& d2, float& d3,
                                         unsigned int a0, unsigned int a1,
                                         unsigned int a2, unsigned int a3,
                                         unsigned int b0, unsigned int b1) {
    asm("mma.sync.aligned.m16n8k8.row.col.f32.tf32.tf32.f32 "
        "{%0,%1,%2,%3},{%4,%5,%6,%7},{%8,%9},{%0,%1,%2,%3};"
        : "+f"(d0), "+f"(d1), "+f"(d2), "+f"(d3)
        : "r"(a0), "r"(a1), "r"(a2), "r"(a3), "r"(b0), "r"(b1));
}

// Prepped tables.
__device__ float g_wa1[12 * 8 * 32 * 4];   // qkv A-frags  [mt][oct][lane][r], tf32
__device__ float g_wa2[4 * 72 * 32 * 4];   // conv A-frags [mt][oct][lane][r], tf32
__device__ float g_wd3[64 * 1024];         // w_deconv B-frags [n][w][koct][npair][lane][4], tf32
__device__ float g_wpt[64 * 64];           // w_proj [j][o]

__global__ void prep_kernel(const float* __restrict__ wq,
                            const float* __restrict__ wk,
                            const float* __restrict__ wv,
                            const float* __restrict__ w_rel,
                            const float* __restrict__ w_deconv,
                            const float* __restrict__ w_proj)
{
    const int i0 = blockIdx.x * blockDim.x + threadIdx.x;
    const int stride = gridDim.x * blockDim.x;
    for (int i = i0; i < 4096; i += stride) {
        int o = i >> 6, c = i & 63;
        g_wpt[(c << 6) | o] = w_proj[i];
    }
    for (int j = i0; j < 12288; j += stride) {
        int r = j & 3, lane = (j >> 2) & 31, oct = (j >> 7) & 7, mt = j >> 10;
        int row = (lane >> 2) + ((r & 1) << 3);
        int k   = oct * 8 + (lane & 3) + ((r >> 1) << 2);
        const float* W = (mt < 4) ? wq : (mt < 8) ? wk : wv;
        g_wa1[j] = __uint_as_float(f2tf32(W[((mt & 3) * 16 + row) * 64 + k]));
    }
    for (int j = i0; j < 36864; j += stride) {
        int r = j & 3, lane = (j >> 2) & 31;
        int mo = j >> 7;
        int mt = mo / 72, oct = mo - mt * 72;
        int u = oct >> 3, jj = oct & 7;
        int ch = mt * 16 + (lane >> 2) + ((r & 1) << 3);
        int c  = jj * 8 + (lane & 3) + ((r >> 1) << 2);
        g_wa2[j] = __uint_as_float(f2tf32(w_rel[ch * 576 + c * 9 + u]));
    }
    // g_wd3: B[k=ch][c2], c2 = bd*16 + e (cols w*32..+31 per warp w).
    // idx = ((((n*8 + w)*8 + koct)*2 + npair)*32 + lane)*4 + v
    for (int j = i0; j < 65536; j += stride) {
        int v    = j & 3;
        int lane = (j >> 2) & 31;
        int rest = j >> 7;
        int npair = rest & 1;
        int koct  = (rest >> 1) & 7;
        int w2    = (rest >> 4) & 7;
        int n     = rest >> 7;
        int noct = npair * 2 + (v >> 1);
        int ch   = koct * 8 + (lane & 3) + (v & 1) * 4;
        int c2   = w2 * 32 + noct * 8 + (lane >> 2);
        int e    = c2 & 15;
        int bd   = c2 >> 4;
        g_wd3[j] = __uint_as_float(f2tf32(w_deconv[ch * 1024 + (n * 16 + e) * 16 + bd]));
    }
}

// Dynamic smem layout (floats), total 20992 (83968 B):
//   PB(pi)=pi*4608 : per-patch scratch (4608)
//     P0-P2 : sp_pad [sig(c)][37] = PB+0..2367 ; sp_lin [c][24] = PB+2368..3903
//     P2    : partials [8w][16][18] = PB+0..2303
//     P4    : hbuf PB+0..1023, wbuf PB+1024..2047, abuf PB+2048..3071
//   QT=9216  : q_t[pi][n][ac][20] (pi*1280 + n*320)
//   KT=11776 : k_t same
//   VS=14336 : v_s[pi][n][dv][18] (pi*1152 + n*288)
//   RC=16640 : relc_t[pi][ac][68] (pi*1088), values pre-cvt'd to tf32
//   CS=18816 : csum[pi][64]
//   RL=18944 : rl[pi][n][ac][16] (pi*1024)
#define SMEM_FLOATS 20992
#define QT 9216
#define KT 11776
#define VS 14336
#define RC 16640
#define CS 18816
#define RL 18944

__global__ __launch_bounds__(256, 2)
void selfattn2d_kernel(const float* __restrict__ x,
                       const float* __restrict__ w_sf1,
                       const float* __restrict__ b_sf1,
                       const float* __restrict__ w_sf2,
                       const float* __restrict__ b_sf2,
                       const float* __restrict__ b_proj,
                       float* __restrict__ out)
{
    extern __shared__ __align__(16) float S[];
    const int bid = blockIdx.x;
    const int b   = bid >> 9;
    const int t  = threadIdx.x;
    const int lane = t & 31;
    const int w    = t >> 5;

    int oys[2], oxs[2];
#pragma unroll
    for (int pi = 0; pi < 2; pi++) {
        int pb = bid * 2 + pi;
        oys[pi] = (pb >> 5) & 31;
        oxs[pi] = pb & 31;
    }

    // ---------------- Phase 0: load both patches ----------------
    {
        const float* xb = x + b * (64 * 64 * 64);
        for (int idx = t; idx < 4608; idx += 256) {
            int pi = (idx >= 2304) ? 1 : 0;
            int local = idx - pi * 2304;
            int c  = local / 36;
            int r  = local - c * 36;
            int ii = r / 6;
            int jj = r - ii * 6;
            int gy = oys[pi] * 2 + ii - 2;
            int gx = oxs[pi] * 2 + jj - 2;
            float val = 0.f;
            bool inpatch = (ii >= 1 && ii <= 4 && jj >= 1 && jj <= 4);
            if (inpatch && gy >= 0 && gy < 64 && gx >= 0 && gx < 64)
                val = xb[c * 4096 + gy * 64 + gx];
            val = __uint_as_float(f2tf32(val));
            S[pi * 4608 + ((c & 15) * 4 + (c >> 4)) * 37 + r] = val;
            if (inpatch)
                S[pi * 4608 + 2368 + c * 24 + (ii - 1) * 4 + (jj - 1)] = val;
        }
    }
    __syncthreads();

    // ---------------- Phase 1: q/k/v on tensor cores ----------------
    // tiles 0-3: q -> q_t (transposed), 4-7: k -> k_t, 8-11: v -> v_s
    {
        const int base0 = (lane & 3) * 24 + (lane >> 2);
        const int g = lane >> 2, tg = lane & 3;
        const int nt = (w < 4) ? 1 : 2;
#pragma unroll
        for (int ti = 0; ti < 2; ti++) {
            if (ti >= nt) break;
            const int mt = (ti == 0) ? w : (w + 4);
            float acc[2][8];
#pragma unroll
            for (int pi = 0; pi < 2; pi++)
#pragma unroll
                for (int p = 0; p < 8; p++) acc[pi][p] = 0.f;
            const float4* wa = ((const float4*)g_wa1) + mt * 256 + lane;
#pragma unroll
            for (int oct = 0; oct < 8; oct++) {
                float4 A4 = wa[oct * 32];
#pragma unroll
                for (int pi = 0; pi < 2; pi++) {
                    const float* bp = S + pi * 4608 + 2368 + base0 + oct * 192;
                    float b0 = bp[0], b1 = bp[96];
                    float c0 = bp[8], c1 = bp[104];
                    mma_tf32(acc[pi][0], acc[pi][1], acc[pi][2], acc[pi][3],
                             fu(A4.x), fu(A4.y), fu(A4.z), fu(A4.w), fu(b0), fu(b1));
                    mma_tf32(acc[pi][4], acc[pi][5], acc[pi][6], acc[pi][7],
                             fu(A4.x), fu(A4.y), fu(A4.z), fu(A4.w), fu(c0), fu(c1));
                }
            }
            if (mt < 8) {
                const float sc = (mt < 4) ? 0.25f : 1.0f;
                const int n2 = mt & 3;
                float* tb = S + ((mt < 4) ? QT : KT) + n2 * 320;
#pragma unroll
                for (int pi = 0; pi < 2; pi++) {
                    float* bp2 = tb + pi * 1280;
                    bp2[(2 * tg) * 20 + g]         = acc[pi][0] * sc;
                    bp2[(2 * tg + 1) * 20 + g]     = acc[pi][1] * sc;
                    bp2[(2 * tg) * 20 + g + 8]     = acc[pi][2] * sc;
                    bp2[(2 * tg + 1) * 20 + g + 8] = acc[pi][3] * sc;
                    bp2[(2 * tg + 8) * 20 + g]         = acc[pi][4] * sc;
                    bp2[(2 * tg + 9) * 20 + g]         = acc[pi][5] * sc;
                    bp2[(2 * tg + 8) * 20 + g + 8]     = acc[pi][6] * sc;
                    bp2[(2 * tg + 9) * 20 + g + 8]     = acc[pi][7] * sc;
                }
            } else {
                const int n2 = mt - 8;
                const int col = 2 * tg;
#pragma unroll
                for (int pi = 0; pi < 2; pi++) {
                    float* dst = S + VS + pi * 1152 + n2 * 288;
                    *(float2*)(dst + g * 18 + col)           = make_float2(acc[pi][0], acc[pi][1]);
                    *(float2*)(dst + (g + 8) * 18 + col)     = make_float2(acc[pi][2], acc[pi][3]);
                    *(float2*)(dst + g * 18 + col + 8)       = make_float2(acc[pi][4], acc[pi][5]);
                    *(float2*)(dst + (g + 8) * 18 + col + 8) = make_float2(acc[pi][6], acc[pi][7]);
                }
            }
        }
    }

    // ---------------- Phase 2: rel_c conv on tensor cores ----------------
    {
        const int mt = w & 3, halfk = w >> 2;
        float acc[2][8];
#pragma unroll
        for (int pi = 0; pi < 2; pi++)
#pragma unroll
            for (int p = 0; p < 8; p++) acc[pi][p] = 0.f;
        const float4* wa = ((const float4*)g_wa2) + mt * 2304 + lane;
        const int q37 = (lane & 3) * 148;
        const int ac = lane >> 2;
        const int Pa = (ac >> 2) * 6 + (ac & 3);
#pragma unroll
        for (int u = 0; u < 9; u++) {
            bool mine = (halfk == 0) ? (u < 5) : (u >= 5);
            if (mine) {
                const int P = Pa + (u / 3) * 6 + (u % 3);
#pragma unroll
                for (int j = 0; j < 8; j++) {
                    float4 A4 = wa[(u * 8 + j) * 32];
                    const int boff = q37 + (j & 1) * 1184 + (j >> 1) * 37 + P;
#pragma unroll
                    for (int pi = 0; pi < 2; pi++) {
                        const float* sp = S + pi * 4608 + boff;
                        float b0 = sp[0],  b1 = sp[592];
                        float c0 = sp[12], c1 = sp[604];
                        mma_tf32(acc[pi][0], acc[pi][1], acc[pi][2], acc[pi][3],
                                 fu(A4.x), fu(A4.y), fu(A4.z), fu(A4.w), fu(b0), fu(b1));
                        mma_tf32(acc[pi][4], acc[pi][5], acc[pi][6], acc[pi][7],
                                 fu(A4.x), fu(A4.y), fu(A4.z), fu(A4.w), fu(c0), fu(c1));
                    }
                }
            }
        }
        __syncthreads();     // patch reads done before partials overwrite
        const int row = lane >> 2, col = 2 * (lane & 3);
#pragma unroll
        for (int pi = 0; pi < 2; pi++) {
            float* rp = S + pi * 4608 + w * 288;
            *(float2*)(rp + row * 18 + col)           = make_float2(acc[pi][0], acc[pi][1]);
            *(float2*)(rp + (row + 8) * 18 + col)     = make_float2(acc[pi][2], acc[pi][3]);
            *(float2*)(rp + row * 18 + col + 8)       = make_float2(acc[pi][4], acc[pi][5]);
            *(float2*)(rp + (row + 8) * 18 + col + 8) = make_float2(acc[pi][6], acc[pi][7]);
        }
    }
    __syncthreads();
    // reduce u-halves into relc_t[pi][ac][ch], pre-converted to tf32
    {
#pragma unroll
        for (int it = 0; it < 2; it++) {
            int task = t + it * 256;
            int pi = task >> 8;
            int rem = task & 255;
            int ac2 = rem >> 4;
            int chq = rem & 15;
            int mt2 = chq >> 2;
            const float* pa = S + pi * 4608 + mt2 * 288 + ((chq & 3) * 4) * 18 + ac2;
            const float* pb2 = pa + 4 * 288;
            float4 v4;
            v4.x = __uint_as_float(f2tf32(pa[0]  + pb2[0]));
            v4.y = __uint_as_float(f2tf32(pa[18] + pb2[18]));
            v4.z = __uint_as_float(f2tf32(pa[36] + pb2[36]));
            v4.w = __uint_as_float(f2tf32(pa[54] + pb2[54]));
            *(float4*)(S + RC + pi * 1088 + ac2 * 68 + chq * 4) = v4;
        }
    }
    __syncthreads();

    // ---------------- Phase 3: GEMM + in-register e-contraction ----------------
    // warp w owns cols c2 in [w*32, w*32+32) => bd in {2w, 2w+1}, all 16 e's.
    {
        const int g = lane >> 2, tg = lane & 3;
#pragma unroll
        for (int n = 0; n < 4; n++) {
            float acc[2][4][4];   // [pi][no][r]
#pragma unroll
            for (int pi = 0; pi < 2; pi++)
#pragma unroll
                for (int no = 0; no < 4; no++)
#pragma unroll
                    for (int r = 0; r < 4; r++) acc[pi][no][r] = 0.f;
            const float4* wd4 = ((const float4*)g_wd3) + ((n * 8 + w) * 8) * 2 * 32 + lane;
#pragma unroll
            for (int koct = 0; koct < 8; koct++) {
                unsigned int a[2][4];
#pragma unroll
                for (int pi = 0; pi < 2; pi++) {
                    const float* rc = S + RC + pi * 1088 + koct * 8 + tg;
                    a[pi][0] = fu(rc[g * 68]);
                    a[pi][1] = fu(rc[(g + 8) * 68]);
                    a[pi][2] = fu(rc[g * 68 + 4]);
                    a[pi][3] = fu(rc[(g + 8) * 68 + 4]);
                }
#pragma unroll
                for (int npair = 0; npair < 2; npair++) {
                    float4 B4 = wd4[(koct * 2 + npair) * 32];
#pragma unroll
                    for (int pi = 0; pi < 2; pi++) {
                        mma_tf32(acc[pi][npair * 2][0], acc[pi][npair * 2][1],
                                 acc[pi][npair * 2][2], acc[pi][npair * 2][3],
                                 a[pi][0], a[pi][1], a[pi][2], a[pi][3],
                                 fu(B4.x), fu(B4.y));
                        mma_tf32(acc[pi][npair * 2 + 1][0], acc[pi][npair * 2 + 1][1],
                                 acc[pi][npair * 2 + 1][2], acc[pi][npair * 2 + 1][3],
                                 a[pi][0], a[pi][1], a[pi][2], a[pi][3],
                                 fu(B4.z), fu(B4.w));
                    }
                }
            }
            // e-contraction: lane holds e = {2tg,2tg+1,8+2tg,8+2tg+1} per (row,bd)
#pragma unroll
            for (int pi = 0; pi < 2; pi++) {
                const float* qt = S + QT + pi * 1280 + n * 320;
                float2 qg0 = *(const float2*)(qt + g * 20 + 2 * tg);
                float2 qg1 = *(const float2*)(qt + g * 20 + 8 + 2 * tg);
                float2 qh0 = *(const float2*)(qt + (g + 8) * 20 + 2 * tg);
                float2 qh1 = *(const float2*)(qt + (g + 8) * 20 + 8 + 2 * tg);
                float r_[4];
                // [0]: row g,   bd=2w   (no 0,1)   [1]: row g,   bd=2w+1 (no 2,3)
                // [2]: row g+8, bd=2w   (no 0,1)   [3]: row g+8, bd=2w+1 (no 2,3)
                r_[0] = qg0.x * acc[pi][0][0] + qg0.y * acc[pi][0][1]
                      + qg1.x * acc[pi][1][0] + qg1.y * acc[pi][1][1];
                r_[1] = qg0.x * acc[pi][2][0] + qg0.y * acc[pi][2][1]
                      + qg1.x * acc[pi][3][0] + qg1.y * acc[pi][3][1];
                r_[2] = qh0.x * acc[pi][0][2] + qh0.y * acc[pi][0][3]
                      + qh1.x * acc[pi][1][2] + qh1.y * acc[pi][1][3];
                r_[3] = qh0.x * acc[pi][2][2] + qh0.y * acc[pi][2][3]
                      + qh1.x * acc[pi][3][2] + qh1.y * acc[pi][3][3];
#pragma unroll
                for (int i = 0; i < 4; i++) {
                    r_[i] += __shfl_xor_sync(0xffffffffu, r_[i], 1);
                    r_[i] += __shfl_xor_sync(0xffffffffu, r_[i], 2);
                }
                if (tg == 0) {
                    float* rl = S + RL + pi * 1024 + n * 256;
                    rl[g * 16 + 2 * w]           = r_[0];
                    rl[g * 16 + 2 * w + 1]       = r_[1];
                    rl[(g + 8) * 16 + 2 * w]     = r_[2];
                    rl[(g + 8) * 16 + 2 * w + 1] = r_[3];
                }
            }
        }
    }
    __syncthreads();

    // ---------------- Phase 4: MLP + softmax + attention (256 threads) ----------------
    {
        const int pi = t >> 7, tl = t & 127;
        const int n = tl >> 5, p = (tl >> 1) & 15, hf = tl & 1;
        const float4* q4 = (const float4*)(S + QT + pi * 1280 + n * 320 + p * 20);
        const float4* k4 = (const float4*)(S + KT + pi * 1280 + n * 320 + p * 20);
        float qv[16], kv[16];
#pragma unroll
        for (int i4 = 0; i4 < 4; i4++) {
            float4 a = q4[i4], c = k4[i4];
            qv[4 * i4] = a.x; qv[4 * i4 + 1] = a.y; qv[4 * i4 + 2] = a.z; qv[4 * i4 + 3] = a.w;
            kv[4 * i4] = c.x; kv[4 * i4 + 1] = c.y; kv[4 * i4 + 2] = c.z; kv[4 * i4 + 3] = c.w;
        }
        float h1v[8];
#pragma unroll
        for (int hh = 0; hh < 8; hh++) {
            int h = hf * 8 + hh;
            float s = b_sf1[h];
            const float* w1r = w_sf1 + h * 32;
#pragma unroll
            for (int d = 0; d < 16; d++) s += w1r[d] * qv[d];
#pragma unroll
            for (int d = 0; d < 16; d++) s += w1r[16 + d] * kv[d];
            h1v[hh] = tanhf(s);
        }
        float* hb = S + pi * 4608 + (n * 16 + p) * 16 + hf * 8;
        *(float4*)hb       = make_float4(h1v[0], h1v[1], h1v[2], h1v[3]);
        *(float4*)(hb + 4) = make_float4(h1v[4], h1v[5], h1v[6], h1v[7]);
    }
    __syncthreads();
    {
        const int pi = t >> 7, tl = t & 127;
        const int n = tl >> 5, p = (tl >> 1) & 15, hf = tl & 1;
        float hv[16];
        const float4* hb4 = (const float4*)(S + pi * 4608 + (n * 16 + p) * 16);
#pragma unroll
        for (int i4 = 0; i4 < 4; i4++) {
            float4 v4 = hb4[i4];
            hv[4 * i4] = v4.x; hv[4 * i4 + 1] = v4.y; hv[4 * i4 + 2] = v4.z; hv[4 * i4 + 3] = v4.w;
        }
        const float* rp = S + RL + pi * 1024 + n * 256 + p * 16;
        float lg[8];
        float mx = -1e30f;
#pragma unroll
        for (int mm = 0; mm < 8; mm++) {
            int m = hf * 8 + mm;
            float s = b_sf2[m];
            const float* w2r = w_sf2 + m * 16;
#pragma unroll
            for (int h = 0; h < 16; h++) s += w2r[h] * hv[h];
            s += rp[m];
            lg[mm] = s;
            mx = fmaxf(mx, s);
        }
        mx = fmaxf(mx, __shfl_xor_sync(0xffffffffu, mx, 1));
        float den = 0.f;
#pragma unroll
        for (int mm = 0; mm < 8; mm++) { lg[mm] = __expf(lg[mm] - mx); den += lg[mm]; }
        den += __shfl_xor_sync(0xffffffffu, den, 1);
        const float inv = 1.0f / den;
        float* wb = S + pi * 4608 + 1024 + (n * 16 + p) * 16 + hf * 8;
        *(float4*)wb       = make_float4(lg[0] * inv, lg[1] * inv, lg[2] * inv, lg[3] * inv);
        *(float4*)(wb + 4) = make_float4(lg[4] * inv, lg[5] * inv, lg[6] * inv, lg[7] * inv);
    }
    __syncthreads();
    {
        const int pi = t >> 7, tl = t & 127;
        const int n = tl >> 5, p = (tl >> 1) & 15, hf = tl & 1;
        float wv_[16];
        const float4* wb4 = (const float4*)(S + pi * 4608 + 1024 + (n * 16 + p) * 16);
#pragma unroll
        for (int i4 = 0; i4 < 4; i4++) {
            float4 v4 = wb4[i4];
            wv_[4 * i4] = v4.x; wv_[4 * i4 + 1] = v4.y; wv_[4 * i4 + 2] = v4.z; wv_[4 * i4 + 3] = v4.w;
        }
        float av[8];
        const float* vbase = S + VS + pi * 1152 + n * 288;
#pragma unroll
        for (int dd = 0; dd < 8; dd++) {
            int dv = hf * 8 + dd;
            const float2* vr = (const float2*)(vbase + dv * 18);
            float a = 0.f;
#pragma unroll
            for (int m2 = 0; m2 < 8; m2++) {
                float2 vv = vr[m2];
                a += wv_[2 * m2] * vv.x + wv_[2 * m2 + 1] * vv.y;
            }
            av[dd] = a;
        }
        float* ab = S + pi * 4608 + 2048 + (n * 16 + p) * 16 + hf * 8;
        *(float4*)ab       = make_float4(av[0], av[1], av[2], av[3]);
        *(float4*)(ab + 4) = make_float4(av[4], av[5], av[6], av[7]);
    }
    __syncthreads();
    if (t < 128) {
        const int pi = t >> 6, tl = t & 63;
        const int plo = tl >> 4;
        const int dv  = tl & 15;
        const float* ab = S + pi * 4608 + 2048;
        float s = 0.f;
#pragma unroll
        for (int n2 = 0; n2 < 4; n2++)
#pragma unroll
            for (int ph = 0; ph < 4; ph++)
                s += ab[(n2 * 16 + ph * 4 + plo) * 16 + dv];
        S[CS + pi * 64 + tl] = s;
    }
    __syncthreads();

    // ---------------- Phase 5: projection + sum ----------------
    if (t < 128) {
        const int pi = t >> 6, o = t & 63;
        const float* cs = S + CS + pi * 64;
        float acc = 16.0f * b_proj[o];
#pragma unroll 8
        for (int j = 0; j < 64; j++) acc += cs[j] * g_wpt[(j << 6) | o];
        out[b * 65536 + o * 1024 + oys[pi] * 32 + oxs[pi]] = acc;
    }
}

extern "C" void kernel_launch(void* const* d_in, const int* in_sizes, int n_in,
                              void* d_out, int out_size)
{
    (void)in_sizes; (void)n_in; (void)out_size;
    cudaFuncSetAttribute(selfattn2d_kernel,
                         cudaFuncAttributeMaxDynamicSharedMemorySize,
                         SMEM_FLOATS * sizeof(float));
    prep_kernel<<<64, 256>>>(
        (const float*)d_in[1],  // wq
        (const float*)d_in[2],  // wk
        (const float*)d_in[3],  // wv
        (const float*)d_in[4],  // w_rel
        (const float*)d_in[5],  // w_deconv
        (const float*)d_in[10]);// w_proj
    selfattn2d_kernel<<<2048, 256, SMEM_FLOATS * sizeof(float)>>>(
        (const float*)d_in[0],  // x
        (const float*)d_in[6],  // w_sf1
        (const float*)d_in[7],  // b_sf1
        (const float*)d_in[8],  // w_sf2
        (const float*)d_in[9],  // b_sf2
        (const float*)d_in[11], // b_proj
        (float*)d_out);
}